// round 12
// baseline (speedup 1.0000x reference)
#include <cuda_runtime.h>
#include <cstdint>
#include <cstddef>

#define BT    4
#define NN    2048
#define FIN   512
#define FOUT  128
#define PIN   256
#define POUT  128
#define HEAD  4
#define KD    32

typedef unsigned long long u64;

// Scratch (device globals; no allocation allowed)
__device__ float g_x   [2*BT*NN*POUT];   // init linear output, fp32 (residual)
__device__ float g_xhi [2*BT*NN*POUT];   // tf32-hi split of g_x
__device__ float g_xlo [2*BT*NN*POUT];   // tf32-lo split of g_x
__device__ float g_xh  [2*BT*NN*POUT];   // proj output, stored as tf32 bits
__device__ float g_G   [2*BT*NN*POUT];   // PPIGE output
__device__ float g_pq2 [2*BT*NN*8];      // per row, head: {P=e^{s1}, Q=e^{.2 s1}}
__device__ float g_uv2 [2*BT*NN*8];      // per col, head: {U=e^{t}, V=e^{.2 t}}
__device__ float g_hgge[2*BT*FOUT];
__device__ float g_sc  [2*BT*NN];
__device__ float g_smax[2*BT*8];
__device__ float g_esum[2*BT*8];
__device__ float g_wpart[2*BT*8*128];
// preconverted weights (tf32 hi/lo splits)
__device__ float g_WhiA[POUT*PIN], g_WloA[POUT*PIN];
__device__ float g_WhiP[POUT*POUT], g_WloP[POUT*POUT];

#define CVT_TF32(o, i) asm("cvt.rna.tf32.f32 %0, %1;" : "=r"(o) : "f"(i))

#define MMA_TF32(d, a, bb) \
    asm("mma.sync.aligned.m16n8k8.row.col.f32.tf32.tf32.f32 " \
        "{%0,%1,%2,%3}, {%4,%5,%6,%7}, {%8,%9}, {%0,%1,%2,%3};" \
        : "+f"((d)[0]), "+f"((d)[1]), "+f"((d)[2]), "+f"((d)[3]) \
        : "r"((a)[0]), "r"((a)[1]), "r"((a)[2]), "r"((a)[3]), \
          "r"((bb)[0]), "r"((bb)[1]))

#define CP_ASYNC16(dst, src) \
    asm volatile("cp.async.cg.shared.global [%0], [%1], 16;" :: "r"(dst), "l"(src))
#define CP_COMMIT() asm volatile("cp.async.commit_group;")
#define CP_WAIT0()  asm volatile("cp.async.wait_group 0;" ::: "memory")

__device__ __forceinline__ void split4(float4 v, uint4& hi, uint4& lo) {
    CVT_TF32(hi.x, v.x); CVT_TF32(hi.y, v.y);
    CVT_TF32(hi.z, v.z); CVT_TF32(hi.w, v.w);
    float lx = v.x - __uint_as_float(hi.x);
    float ly = v.y - __uint_as_float(hi.y);
    float lz = v.z - __uint_as_float(hi.z);
    float lw = v.w - __uint_as_float(hi.w);
    CVT_TF32(lo.x, lx); CVT_TF32(lo.y, ly);
    CVT_TF32(lo.z, lz); CVT_TF32(lo.w, lw);
}

// ---------------------------------------------------------------------------
// Weight preconversion: tf32 hi/lo splits of initW, projW.
// ---------------------------------------------------------------------------
__global__ __launch_bounds__(256) void wprep_kernel(
    const float* __restrict__ initW, const float* __restrict__ projW)
{
    int idx = blockIdx.x*256 + threadIdx.x;  // float4 index
    if (idx < 8192) {
        float4 v = *(const float4*)&initW[idx*4];
        uint4 hi, lo; split4(v, hi, lo);
        *(uint4*)&g_WhiA[idx*4] = hi;
        *(uint4*)&g_WloA[idx*4] = lo;
    } else if (idx < 12288) {
        int j = idx - 8192;
        float4 v = *(const float4*)&projW[j*4];
        uint4 hi, lo; split4(v, hi, lo);
        *(uint4*)&g_WhiP[j*4] = hi;
        *(uint4*)&g_WloP[j*4] = lo;
    }
}

// ---------------------------------------------------------------------------
// Split-tf32 GEMM (3-term compensation).  CTA 128x128, 512 thr.
// mode 0: A = bio fp32 (K=256, CVT on the fly), W from g_W*A (cp.async).
//         Epilogue writes g_x AND its hi/lo split.
// mode 1: A = g_xhi/g_xlo (cp.async), W from g_W*P; attention-scalar epilogue.
// ---------------------------------------------------------------------------
#define GS 36
#define GEMM_SM_BYTES (4*128*GS*4)

__global__ __launch_bounds__(512) void gemm_mma(
    const float* __restrict__ A0, const float* __restrict__ A1,
    const float* __restrict__ bias,
    const float* __restrict__ attw, const float* __restrict__ attb,
    int Kdim, int mode)
{
    extern __shared__ float sg[];
    float* Ahi = sg;
    float* Alo = sg + 128*GS;
    float* Whi = sg + 2*128*GS;
    float* Wlo = sg + 3*128*GS;
    const unsigned sAhi = (unsigned)__cvta_generic_to_shared(Ahi);
    const unsigned sAlo = (unsigned)__cvta_generic_to_shared(Alo);
    const unsigned sWhi = (unsigned)__cvta_generic_to_shared(Whi);
    const unsigned sWlo = (unsigned)__cvta_generic_to_shared(Wlo);

    const int branch = blockIdx.y;
    const float* Ain = nullptr;
    const float *Asrc_hi, *Asrc_lo, *Wsrc_hi, *Wsrc_lo;
    float* Cout;
    if (mode == 0) {
        Ain = branch ? A1 : A0;
        Asrc_hi = nullptr; Asrc_lo = nullptr;
        Wsrc_hi = g_WhiA; Wsrc_lo = g_WloA;
        Cout = g_x;
    } else {
        Asrc_hi = g_xhi + (size_t)branch*8192*POUT;
        Asrc_lo = g_xlo + (size_t)branch*8192*POUT;
        Wsrc_hi = g_WhiP; Wsrc_lo = g_WloP;
        Cout = g_xh;
    }
    Cout += (size_t)branch*8192*POUT;

    const int row0 = blockIdx.x * 128;
    const int tid = threadIdx.x, lane = tid & 31, warp = tid >> 5;
    const int g = lane >> 2, t = lane & 3;
    const int mr = warp >> 2, nc = warp & 3;

    float d[2][4][4];
#pragma unroll
    for (int mb = 0; mb < 2; mb++)
#pragma unroll
        for (int nt = 0; nt < 4; nt++)
#pragma unroll
            for (int q = 0; q < 4; q++) d[mb][nt][q] = 0.f;

    for (int kc = 0; kc < Kdim; kc += 32) {
        __syncthreads();
        // W tiles: pure cp.async from preconverted arrays
#pragma unroll
        for (int p = 0; p < 2; p++) {
            int idx = tid + p*512, r = idx >> 3, kq = idx & 7;
            unsigned off = (unsigned)(r*GS + kq*4)*4u;
            CP_ASYNC16(sWhi + off, &Wsrc_hi[(size_t)r*Kdim + kc + kq*4]);
            CP_ASYNC16(sWlo + off, &Wsrc_lo[(size_t)r*Kdim + kc + kq*4]);
        }
        if (mode == 0) {
            // A: fp32 load + split + STS
#pragma unroll
            for (int p = 0; p < 2; p++) {
                int idx = tid + p*512, r = idx >> 3, kq = idx & 7;
                float4 v = *(const float4*)&Ain[(size_t)(row0 + r)*Kdim + kc + kq*4];
                uint4 hi, lo; split4(v, hi, lo);
                *(uint4*)&Ahi[r*GS + kq*4] = hi;
                *(uint4*)&Alo[r*GS + kq*4] = lo;
            }
        } else {
#pragma unroll
            for (int p = 0; p < 2; p++) {
                int idx = tid + p*512, r = idx >> 3, kq = idx & 7;
                unsigned off = (unsigned)(r*GS + kq*4)*4u;
                CP_ASYNC16(sAhi + off, &Asrc_hi[(size_t)(row0 + r)*Kdim + kc + kq*4]);
                CP_ASYNC16(sAlo + off, &Asrc_lo[(size_t)(row0 + r)*Kdim + kc + kq*4]);
            }
        }
        CP_COMMIT();
        CP_WAIT0();
        __syncthreads();
#pragma unroll
        for (int k8 = 0; k8 < 4; k8++) {
            const int kb = k8*8;
            unsigned ahi[2][4], alo[2][4];
#pragma unroll
            for (int mb = 0; mb < 2; mb++) {
                int base = (mr*32 + mb*16 + g)*GS + kb;
                ahi[mb][0] = __float_as_uint(Ahi[base + t]);
                ahi[mb][1] = __float_as_uint(Ahi[base + 8*GS + t]);
                ahi[mb][2] = __float_as_uint(Ahi[base + t + 4]);
                ahi[mb][3] = __float_as_uint(Ahi[base + 8*GS + t + 4]);
                alo[mb][0] = __float_as_uint(Alo[base + t]);
                alo[mb][1] = __float_as_uint(Alo[base + 8*GS + t]);
                alo[mb][2] = __float_as_uint(Alo[base + t + 4]);
                alo[mb][3] = __float_as_uint(Alo[base + 8*GS + t + 4]);
            }
#pragma unroll
            for (int nt = 0; nt < 4; nt++) {
                int cb = (nc*32 + nt*8 + g)*GS + kb;
                unsigned bhi[2], blo[2];
                bhi[0] = __float_as_uint(Whi[cb + t]);
                bhi[1] = __float_as_uint(Whi[cb + t + 4]);
                blo[0] = __float_as_uint(Wlo[cb + t]);
                blo[1] = __float_as_uint(Wlo[cb + t + 4]);
#pragma unroll
                for (int mb = 0; mb < 2; mb++) {
                    MMA_TF32(d[mb][nt], ahi[mb], bhi);
                    MMA_TF32(d[mb][nt], ahi[mb], blo);
                    MMA_TF32(d[mb][nt], alo[mb], bhi);
                }
            }
        }
    }

    float2 bv[4];
#pragma unroll
    for (int nt = 0; nt < 4; nt++) {
        int c = nc*32 + nt*8 + 2*t;
        if (bias) bv[nt] = *(const float2*)&bias[c];
        else      bv[nt] = make_float2(0.f, 0.f);
    }

    if (mode == 0) {
        float* Xhi = g_xhi + (size_t)branch*8192*POUT;
        float* Xlo = g_xlo + (size_t)branch*8192*POUT;
#pragma unroll
        for (int mb = 0; mb < 2; mb++)
#pragma unroll
            for (int q = 0; q < 2; q++) {
                int row = row0 + mr*32 + mb*16 + q*8 + g;
#pragma unroll
                for (int nt = 0; nt < 4; nt++) {
                    int c = nc*32 + nt*8 + 2*t;
                    float ox = d[mb][nt][q*2+0] + bv[nt].x;
                    float oy = d[mb][nt][q*2+1] + bv[nt].y;
                    *(float2*)&Cout[(size_t)row*POUT + c] = make_float2(ox, oy);
                    unsigned hx, hy;
                    CVT_TF32(hx, ox); CVT_TF32(hy, oy);
                    float lx = ox - __uint_as_float(hx);
                    float ly = oy - __uint_as_float(hy);
                    unsigned lxu, lyu;
                    CVT_TF32(lxu, lx); CVT_TF32(lyu, ly);
                    *(float2*)&Xhi[(size_t)row*POUT + c] =
                        make_float2(__uint_as_float(hx), __uint_as_float(hy));
                    *(float2*)&Xlo[(size_t)row*POUT + c] =
                        make_float2(__uint_as_float(lxu), __uint_as_float(lyu));
                }
            }
    } else {
        const int h = nc;
        float2 w1v[4], w2v[4];
#pragma unroll
        for (int nt = 0; nt < 4; nt++) {
            int lc = nt*8 + 2*t;
            w1v[nt] = *(const float2*)&attw[h*64 + lc];
            w2v[nt] = *(const float2*)&attw[h*64 + 32 + lc];
        }
        float p1[4] = {0,0,0,0}, p2[4] = {0,0,0,0};
#pragma unroll
        for (int mb = 0; mb < 2; mb++)
#pragma unroll
            for (int nt = 0; nt < 4; nt++) {
                p1[mb*2+0] += d[mb][nt][0]*w1v[nt].x + d[mb][nt][1]*w1v[nt].y;
                p1[mb*2+1] += d[mb][nt][2]*w1v[nt].x + d[mb][nt][3]*w1v[nt].y;
                p2[mb*2+0] += d[mb][nt][0]*w2v[nt].x + d[mb][nt][1]*w2v[nt].y;
                p2[mb*2+1] += d[mb][nt][2]*w2v[nt].x + d[mb][nt][3]*w2v[nt].y;
            }
#pragma unroll
        for (int mb = 0; mb < 2; mb++)
#pragma unroll
            for (int q = 0; q < 2; q++) {
                int row = row0 + mr*32 + mb*16 + q*8 + g;
#pragma unroll
                for (int nt = 0; nt < 4; nt++) {
                    int c = nc*32 + nt*8 + 2*t;
                    unsigned o0, o1;
                    CVT_TF32(o0, d[mb][nt][q*2+0]);
                    CVT_TF32(o1, d[mb][nt][q*2+1]);
                    *(float2*)&Cout[(size_t)row*POUT + c] =
                        make_float2(__uint_as_float(o0), __uint_as_float(o1));
                }
            }
#pragma unroll
        for (int i = 0; i < 4; i++) {
            p1[i] += __shfl_xor_sync(0xffffffffu, p1[i], 1);
            p1[i] += __shfl_xor_sync(0xffffffffu, p1[i], 2);
            p2[i] += __shfl_xor_sync(0xffffffffu, p2[i], 1);
            p2[i] += __shfl_xor_sync(0xffffffffu, p2[i], 2);
        }
        if (t == 0) {
            const float bb = attb[h];
#pragma unroll
            for (int mb = 0; mb < 2; mb++)
#pragma unroll
                for (int q = 0; q < 2; q++) {
                    int row = row0 + mr*32 + mb*16 + q*8 + g;
                    size_t gr = (size_t)branch*8192 + row;
                    float s1 = p1[mb*2+q];
                    float t2 = p2[mb*2+q] + bb;
                    *(float2*)&g_pq2[gr*8 + h*2] =
                        make_float2(__expf(s1), __expf(0.2f*s1));
                    *(float2*)&g_uv2[gr*8 + h*2] =
                        make_float2(__expf(t2), __expf(0.2f*t2));
                }
        }
    }
}

// ---------------------------------------------------------------------------
// GGE fused: grid 8 (branch*BT+sample), 512 thr.
// ---------------------------------------------------------------------------
__global__ __launch_bounds__(512) void gge_kernel(
    const float* __restrict__ a, const float* __restrict__ b,
    const float* __restrict__ W1, const float* __restrict__ b1,
    const float* __restrict__ W2, const float* __restrict__ b2)
{
    __shared__ float in_s[FIN];
    __shared__ float h1[128];
    const int base = blockIdx.x;
    const int br = base >> 2, bi = base & 3;
    const float* in = (br ? b : a) + bi*FIN;
    const int tid = threadIdx.x, warp = tid >> 5, lane = tid & 31;
    if (tid < FIN) in_s[tid] = in[tid];
    __syncthreads();
#pragma unroll
    for (int o = warp; o < 128; o += 16) {
        float acc = 0.f;
#pragma unroll
        for (int q = 0; q < 16; q++) acc += W1[(size_t)o*FIN + lane + q*32] * in_s[lane + q*32];
#pragma unroll
        for (int off = 16; off; off >>= 1) acc += __shfl_xor_sync(0xffffffffu, acc, off);
        if (lane == 0) h1[o] = fmaxf(acc + b1[o], 0.f);
    }
    __syncthreads();
#pragma unroll
    for (int o = warp; o < 128; o += 16) {
        float acc = 0.f;
#pragma unroll
        for (int q = 0; q < 4; q++) acc += W2[o*128 + lane + q*32] * h1[lane + q*32];
#pragma unroll
        for (int off = 16; off; off >>= 1) acc += __shfl_xor_sync(0xffffffffu, acc, off);
        if (lane == 0) g_hgge[base*FOUT + o] = fmaxf(acc + b2[o], 0.f);
    }
}

// ---------------------------------------------------------------------------
// Attention: tf32 mma, cp.async double-buffer, ONE barrier per tile,
// den folded into MMA (ones column).  CTA 64 i x 128 cols, 256 thr.
// ---------------------------------------------------------------------------
#define XH_JS 136
#define TUV_OFF 8704             // floats (64*136)
#define AM_OFF  (TUV_OFF + 512)  // 9216; 64 u64 = 128 floats
#define BUFS    (AM_OFF + 128)   // 9344 floats/buffer
#define ATTN_SM_BYTES (2*BUFS*4) // 74,752

__device__ __forceinline__ void attn_copy(
    float* buf, const float* __restrict__ xhb, const float* __restrict__ uvb,
    int jt, int tid)
{
    unsigned base = (unsigned)__cvta_generic_to_shared(buf);
#pragma unroll
    for (int p = 0; p < 8; p++) {
        int idx = tid + p*256, j = idx >> 5, c = idx & 31;
        unsigned dst = base + (unsigned)(j*XH_JS + c*4)*4u;
        CP_ASYNC16(dst, &xhb[(size_t)(jt + j)*POUT + c*4]);
    }
    if (tid < 128) {
        int j = tid >> 1, hf = tid & 1;
        unsigned dst = base + (unsigned)(TUV_OFF + j*8 + hf*4)*4u;
        CP_ASYNC16(dst, &uvb[(size_t)(jt + j)*8 + hf*4]);
    }
}

__global__ __launch_bounds__(256, 2) void attn_mma(
    const int* __restrict__ A0, const int* __restrict__ A1)
{
    extern __shared__ float smA[];
    float* bufs[2] = { smA, smA + BUFS };

    const int branch = blockIdx.z, b = blockIdx.y;
    const int i0 = blockIdx.x * 64;
    const int tid = threadIdx.x, warp = tid >> 5, lane = tid & 31;
    const int h = warp & 3, ib = warp >> 2;
    const int g = lane >> 2, t = lane & 3;
    const int hk0 = h * 32;
    const unsigned bm1 = 1u << t, bm2 = 16u << t;
    const unsigned one_tf = __float_as_uint(1.0f);
    const unsigned ones[2] = { one_tf, one_tf };

    const size_t rbase = (size_t)(branch*BT + b) * NN;
    const float* xhb = g_xh + rbase * POUT;
    const float* uvb = g_uv2 + rbase * 8;
    const int* Abase = (branch ? A1 : A0) + ((size_t)b*NN + i0) * NN;

    float2 pq[4];
#pragma unroll
    for (int r = 0; r < 4; r++)
        pq[r] = *(const float2*)&g_pq2[(rbase + i0 + ib*32 + g + r*8)*8 + h*2];

    float d[2][4][4];
    float d5[2][4];
#pragma unroll
    for (int mt = 0; mt < 2; mt++) {
#pragma unroll
        for (int q = 0; q < 4; q++) d5[mt][q] = 0.f;
#pragma unroll
        for (int nt = 0; nt < 4; nt++)
#pragma unroll
            for (int q = 0; q < 4; q++) d[mt][nt][q] = 0.f;
    }

    int pfa[16];
    attn_copy(bufs[0], xhb, uvb, 0, tid);
    CP_COMMIT();
    {
        const int* Ar = Abase + (size_t)(warp*8)*NN;
#pragma unroll
        for (int r = 0; r < 8; r++) {
            pfa[2*r]   = Ar[(size_t)r*NN + lane];
            pfa[2*r+1] = Ar[(size_t)r*NN + 32 + lane];
        }
    }

#pragma unroll 1
    for (int it = 0; it < 32; it++) {
        float* cur = bufs[it & 1];
        float* nxt = bufs[(it + 1) & 1];
        {   // ballots -> AM(cur).  Safe pre-wait: disjoint from in-flight xh/uv.
            u64* am = (u64*)(cur + AM_OFF);
#pragma unroll
            for (int r = 0; r < 8; r++) {
                unsigned m0 = __ballot_sync(0xffffffffu, pfa[2*r] != 0);
                unsigned m1 = __ballot_sync(0xffffffffu, pfa[2*r+1] != 0);
                if (lane == 0) am[warp*8 + r] = (u64)m0 | ((u64)m1 << 32);
            }
        }
        CP_WAIT0();
        __syncthreads();   // single barrier: publishes AM + cp.async data;
                           // also guarantees prior-tile reads finished before
                           // the cp.async below overwrites that buffer.
        if (it < 31) {
            attn_copy(nxt, xhb, uvb, (it + 1)*64, tid);
            CP_COMMIT();
            const int* Ar = Abase + (size_t)(warp*8)*NN + (it + 1)*64;
#pragma unroll
            for (int r = 0; r < 8; r++) {
                pfa[2*r]   = Ar[(size_t)r*NN + lane];
                pfa[2*r+1] = Ar[(size_t)r*NN + 32 + lane];
            }
        }

        const u64* ams = (const u64*)(cur + AM_OFF);
        u64 am[4];
#pragma unroll
        for (int r = 0; r < 4; r++) am[r] = ams[ib*32 + g + r*8];
        const float* ts = cur + TUV_OFF;

#pragma unroll
        for (int chunk = 0; chunk < 8; chunk++) {
            const int j0 = chunk * 8;
            unsigned by[4];
#pragma unroll
            for (int r = 0; r < 4; r++) by[r] = (unsigned)(am[r] >> j0);
            float2 Ua = *(const float2*)&ts[(j0 + t)*8 + h*2];
            float2 Ub = *(const float2*)&ts[(j0 + 4 + t)*8 + h*2];

            float w[4][2];
#pragma unroll
            for (int r = 0; r < 4; r++) {
                float ea = fmaxf(pq[r].x * Ua.x, pq[r].y * Ua.y);
                float eb = fmaxf(pq[r].x * Ub.x, pq[r].y * Ub.y);
                w[r][0] = (by[r] & bm1) ? ea : 0.f;
                w[r][1] = (by[r] & bm2) ? eb : 0.f;
            }
            unsigned a0[4], a1[4];
            a0[0] = __float_as_uint(w[0][0]); a0[1] = __float_as_uint(w[1][0]);
            a0[2] = __float_as_uint(w[0][1]); a0[3] = __float_as_uint(w[1][1]);
            a1[0] = __float_as_uint(w[2][0]); a1[1] = __float_as_uint(w[3][0]);
            a1[2] = __float_as_uint(w[2][1]); a1[3] = __float_as_uint(w[3][1]);

            const float* xr0 = &cur[(j0 + t)*XH_JS + hk0 + g];
            const float* xr1 = &cur[(j0 + 4 + t)*XH_JS + hk0 + g];
            unsigned bb[4][2];
#pragma unroll
            for (int nt = 0; nt < 4; nt++) {
                bb[nt][0] = __float_as_uint(xr0[nt*8]);
                bb[nt][1] = __float_as_uint(xr1[nt*8]);
            }
#pragma unroll
            for (int nt = 0; nt < 4; nt++) {
                MMA_TF32(d[0][nt], a0, bb[nt]);
                MMA_TF32(d[1][nt], a1, bb[nt]);
            }
            MMA_TF32(d5[0], a0, ones);
            MMA_TF32(d5[1], a1, ones);
        }
    }

    // epilogue
#pragma unroll
    for (int mt = 0; mt < 2; mt++) {
#pragma unroll
        for (int half = 0; half < 2; half++) {
            const float inv = 1.f / fmaxf(d5[mt][half*2], 1e-30f);
            const size_t row = rbase + i0 + ib*32 + g + mt*16 + half*8;
#pragma unroll
            for (int nt = 0; nt < 4; nt++) {
                const int col = hk0 + nt*8 + 2*t;
                float2 xr = *(const float2*)&g_x[row*POUT + col];
                float2 o;
                o.x = fmaxf(d[mt][nt][half*2+0]*inv, 0.f) + xr.x;
                o.y = fmaxf(d[mt][nt][half*2+1]*inv, 0.f) + xr.y;
                *(float2*)&g_G[row*POUT + col] = o;
            }
        }
    }
}

// ---------------------------------------------------------------------------
// GAGA A: scores + per-segment max.  grid (8, 8), 256 thr.
// ---------------------------------------------------------------------------
__global__ __launch_bounds__(256) void gagaA_kernel()
{
    __shared__ float hv[128];
    __shared__ float red[8];
    const int base = blockIdx.x, seg = blockIdx.y;
    const float* Gp = g_G + (size_t)base * NN * POUT;
    const int tid = threadIdx.x, warp = tid >> 5, lane = tid & 31;

    if (tid < 128) hv[tid] = g_hgge[base*FOUT + tid];
    __syncthreads();
    const int n0 = seg * 256;
    float lmax = -1e30f;
    for (int r = n0 + warp; r < n0 + 256; r += 8) {
        float4 gg = *(const float4*)&Gp[(size_t)r*POUT + lane*4];
        float a = gg.x*hv[lane*4+0] + gg.y*hv[lane*4+1]
                + gg.z*hv[lane*4+2] + gg.w*hv[lane*4+3];
#pragma unroll
        for (int off = 16; off; off >>= 1) a += __shfl_xor_sync(0xffffffffu, a, off);
        if (lane == 0) { g_sc[base*NN + r] = a; lmax = fmaxf(lmax, a); }
    }
    if (lane == 0) red[warp] = lmax;
    __syncthreads();
    if (tid == 0) {
        float m = red[0];
#pragma unroll
        for (int i = 1; i < 8; i++) m = fmaxf(m, red[i]);
        g_smax[base*8 + seg] = m;
    }
}

// ---------------------------------------------------------------------------
// GAGA C: exp + partial expsum + partial weighted sum.  grid (8, 8), 256 thr.
// ---------------------------------------------------------------------------
__global__ __launch_bounds__(256) void gagaC_kernel()
{
    __shared__ float es[256];
    __shared__ float wred[256];
    __shared__ float mx_s;
    const int base = blockIdx.x, seg = blockIdx.y;
    const float* Gp = g_G + (size_t)base * NN * POUT;
    const int tid = threadIdx.x;

    if (tid == 0) {
        float m = g_smax[base*8];
#pragma unroll
        for (int i = 1; i < 8; i++) m = fmaxf(m, g_smax[base*8 + i]);
        mx_s = m;
    }
    __syncthreads();
    const float mx = mx_s;
    const int n0 = seg * 256;
    es[tid] = __expf(g_sc[base*NN + n0 + tid] - mx);
    __syncthreads();

    const int dd = tid & 127, half = tid >> 7;
    float acc = 0.f;
    const int r0 = n0 + half*128;
#pragma unroll 8
    for (int k = 0; k < 128; k++)
        acc += Gp[(size_t)(r0 + k)*POUT + dd] * es[half*128 + k];
    wred[tid] = acc;
    __syncthreads();
    if (tid < 128)
        g_wpart[(base*8 + seg)*128 + tid] = wred[tid] + wred[tid + 128];
    if (tid < 32) {
        float s = es[tid] + es[tid+32] + es[tid+64] + es[tid+96]
                + es[tid+128] + es[tid+160] + es[tid+192] + es[tid+224];
#pragma unroll
        for (int off = 16; off; off >>= 1) s += __shfl_xor_sync(0xffffffffu, s, off);
        if (tid == 0) g_esum[base*8 + tid/32*0 + blockIdx.y] = s;
    }
}

// ---------------------------------------------------------------------------
// LED head + log_softmax (combines gaga partials).  grid BT, 256 thr.
// ---------------------------------------------------------------------------
__global__ __launch_bounds__(256) void led_kernel(
    const float* __restrict__ convW, const float* __restrict__ convb,
    const float* __restrict__ W1, const float* __restrict__ b1,
    const float* __restrict__ W2, const float* __restrict__ b2,
    float* __restrict__ out)
{
    __shared__ float ea[256], eb[256], cat[512], hx[128], lg[2];
    const int bt = blockIdx.x;
    const int tid = threadIdx.x, warp = tid >> 5, lane = tid & 31;

    if (tid < 128) {
#pragma unroll
        for (int br = 0; br < 2; br++) {
            const int base = br*BT + bt;
            float s = 0.f, e = 0.f;
#pragma unroll
            for (int sg = 0; sg < 8; sg++) {
                s += g_wpart[(base*8 + sg)*128 + tid];
                e += g_esum[base*8 + sg];
            }
            float pool = s / e;
            if (br == 0) { ea[tid] = g_hgge[base*FOUT + tid]; ea[128+tid] = pool; }
            else         { eb[tid] = g_hgge[base*FOUT + tid]; eb[128+tid] = pool; }
        }
    }
    __syncthreads();
    for (int o = warp; o < 256; o += 8) {
        float va = 0.f, vb = 0.f;
#pragma unroll
        for (int q = 0; q < 8; q++) {
            float w = convW[(size_t)o*256 + lane + q*32];
            va += ea[lane + q*32] * w;
            vb += eb[lane + q*32] * w;
        }
#pragma unroll
        for (int off = 16; off; off >>= 1) {
            va += __shfl_xor_sync(0xffffffffu, va, off);
            vb += __shfl_xor_sync(0xffffffffu, vb, off);
        }
        if (lane == 0) cat[o] = fmaxf(va, vb) + convb[o];
    }
    if (tid < 256) cat[256 + tid] = ea[tid] - eb[tid];
    __syncthreads();
    for (int o = warp; o < 128; o += 8) {
        float acc = 0.f;
#pragma unroll
        for (int q = 0; q < 16; q++) acc += cat[lane + q*32] * W1[(size_t)o*512 + lane + q*32];
#pragma unroll
        for (int off = 16; off; off >>= 1) acc += __shfl_xor_sync(0xffffffffu, acc, off);
        if (lane == 0) hx[o] = fmaxf(acc + b1[o], 0.f);
    }
    __syncthreads();
    if (warp < 2) {
        float acc = 0.f;
#pragma unroll
        for (int q = 0; q < 4; q++) acc += hx[lane + q*32] * W2[warp*128 + lane + q*32];
#pragma unroll
        for (int off = 16; off; off >>= 1) acc += __shfl_xor_sync(0xffffffffu, acc, off);
        if (lane == 0) lg[warp] = acc + b2[warp];
    }
    __syncthreads();
    if (tid == 0) {
        float l0 = lg[0], l1 = lg[1];
        float m = fmaxf(l0, l1);
        float lse = m + logf(__expf(l0-m) + __expf(l1-m));
        out[bt*2 + 0] = l0 - lse;
        out[bt*2 + 1] = l1 - lse;
    }
}

// ---------------------------------------------------------------------------
extern "C" void kernel_launch(void* const* d_in, const int* in_sizes, int n_in,
                              void* d_out, int out_size)
{
    const float* a      = (const float*)d_in[0];
    const float* bio_a  = (const float*)d_in[1];
    const int*   Aadj   = (const int*)  d_in[2];
    const float* b      = (const float*)d_in[3];
    const float* bio_b  = (const float*)d_in[4];
    const int*   Badj   = (const int*)  d_in[5];
    const float* initW  = (const float*)d_in[6];
    const float* initb  = (const float*)d_in[7];
    const float* projW  = (const float*)d_in[8];
    const float* attw   = (const float*)d_in[9];
    const float* attb   = (const float*)d_in[10];
    const float* ggeW1  = (const float*)d_in[11];
    const float* ggeb1  = (const float*)d_in[12];
    const float* ggeW2  = (const float*)d_in[13];
    const float* ggeb2  = (const float*)d_in[14];
    const float* convW  = (const float*)d_in[15];
    const float* convb  = (const float*)d_in[16];
    const float* ledW1  = (const float*)d_in[17];
    const float* ledb1  = (const float*)d_in[18];
    const float* ledW2  = (const float*)d_in[19];
    const float* ledb2  = (const float*)d_in[20];
    float* out = (float*)d_out;

    cudaFuncSetAttribute(gemm_mma, cudaFuncAttributeMaxDynamicSharedMemorySize,
                         GEMM_SM_BYTES);
    cudaFuncSetAttribute(attn_mma, cudaFuncAttributeMaxDynamicSharedMemorySize,
                         ATTN_SM_BYTES);

    // attn is the 4th launch: profiler capture lands on it
    wprep_kernel<<<48, 256>>>(initW, projW);
    gemm_mma<<<dim3(64, 2), 512, GEMM_SM_BYTES>>>(bio_a, bio_b, initb,
                                                  attw, attb, PIN, 0);
    gemm_mma<<<dim3(64, 2), 512, GEMM_SM_BYTES>>>(nullptr, nullptr, nullptr,
                                                  attw, attb, POUT, 1);
    attn_mma<<<dim3(NN/64, BT, 2), 256, ATTN_SM_BYTES>>>(Aadj, Badj);
    gge_kernel<<<8, 512>>>(a, b, ggeW1, ggeb1, ggeW2, ggeb2);
    gagaA_kernel<<<dim3(2*BT, 8), 256>>>();
    gagaC_kernel<<<dim3(2*BT, 8), 256>>>();
    led_kernel<<<BT, 256>>>(convW, convb, ledW1, ledb1, ledW2, ledb2, out);
}